// round 2
// baseline (speedup 1.0000x reference)
#include <cuda_runtime.h>

#define EPSV 1e-7f
#define NPTS 131072
#define NT3  393216        // NPTS*3
#define NSEG 32

// ---- transposed-weight offsets (in floats) within d_wt ----
#define O_W1F 0
#define O_W1D 16384
#define O_W2F 32768
#define O_W2D 49152
#define O_W3  65536
#define O_WD1 81920
#define O_WR3 98304
#define O_W4F 114688
#define O_W4D 180224
#define O_W5  245760
#define O_WD2 311296
#define O_WR5 376832
#define WT_TOTAL 442368

// ---- static device scratch (no allocations allowed) ----
__device__ float d_wt[WT_TOTAL];
__device__ float d_g3s[128ull * (unsigned long long)NT3];   // vn3 output, layout [c][n*3+j]  (201 MB)
__device__ float d_h5s[256ull * (unsigned long long)NT3];   // vn5 output, layout [c][n*3+j]  (402 MB)
__device__ float d_r3[NSEG * 128 * 3];                      // relu3 output per segment
__device__ unsigned long long d_key1[NSEG * 128];
__device__ unsigned long long d_key2[NSEG * 256];

// ---------------------------------------------------------------------------
// helpers
// ---------------------------------------------------------------------------
__device__ __forceinline__ unsigned long long packkey(float dot, unsigned int n) {
    unsigned int u = __float_as_uint(dot);
    u = (u & 0x80000000u) ? ~u : (u | 0x80000000u);   // order-preserving float->uint
    return ((unsigned long long)u << 32) | (unsigned long long)(0xFFFFFFFFu - n); // tie -> min n
}

__device__ __forceinline__ unsigned long long shfl_xor_u64(unsigned long long v, int m) {
    unsigned int lo = (unsigned int)v;
    unsigned int hi = (unsigned int)(v >> 32);
    lo = __shfl_xor_sync(0xFFFFFFFFu, lo, m);
    hi = __shfl_xor_sync(0xFFFFFFFFu, hi, m);
    return ((unsigned long long)hi << 32) | lo;
}

// Y[o, col] (+)= sum_k W[o,k] * X[k, col]  for the thread's 8x6 tile.
// wT is k-major: wT[k*OTOT + o].  smW holds one (mm_one) or two (mm_pair) 16 x OTOT tiles.
template<int K, int OTOT, int COLS>
__device__ __forceinline__ void mm_pair(const float* __restrict__ wfT, const float* __restrict__ wdT,
                                        const float* __restrict__ bufIn, float* smW,
                                        float accP[8][6], float accD[8][6],
                                        int o_base, int col_base, int tid)
{
    float* smWd = smW + 16 * OTOT;
    for (int k0 = 0; k0 < K; k0 += 16) {
        __syncthreads();
        {
            const float4* s1 = (const float4*)(wfT + k0 * OTOT);
            const float4* s2 = (const float4*)(wdT + k0 * OTOT);
            float4* t1 = (float4*)smW;
            float4* t2 = (float4*)smWd;
#pragma unroll
            for (int r = 0; r < OTOT / 64; r++) {
                t1[tid + 256 * r] = s1[tid + 256 * r];
                t2[tid + 256 * r] = s2[tid + 256 * r];
            }
        }
        __syncthreads();
#pragma unroll
        for (int kk = 0; kk < 16; kk++) {
            const float* ar = smW  + kk * OTOT + o_base;
            const float* dr = smWd + kk * OTOT + o_base;
            const float* br = bufIn + (k0 + kk) * COLS + col_base;
            float b[6];
            float2 b01 = *(const float2*)(br);
            float2 b23 = *(const float2*)(br + 2);
            float2 b45 = *(const float2*)(br + 4);
            b[0] = b01.x; b[1] = b01.y; b[2] = b23.x; b[3] = b23.y; b[4] = b45.x; b[5] = b45.y;
            float af[8], ad[8];
            *(float4*)&af[0] = *(const float4*)(ar);
            *(float4*)&af[4] = *(const float4*)(ar + 4);
            *(float4*)&ad[0] = *(const float4*)(dr);
            *(float4*)&ad[4] = *(const float4*)(dr + 4);
#pragma unroll
            for (int oo = 0; oo < 8; oo++)
#pragma unroll
                for (int cc = 0; cc < 6; cc++) {
                    accP[oo][cc] += af[oo] * b[cc];
                    accD[oo][cc] += ad[oo] * b[cc];
                }
        }
    }
}

template<int K, int OTOT, int COLS>
__device__ __forceinline__ void mm_one(const float* __restrict__ wT,
                                       const float* __restrict__ bufIn, float* smW,
                                       float acc[8][6], int o_base, int col_base, int tid)
{
    for (int k0 = 0; k0 < K; k0 += 16) {
        __syncthreads();
        {
            const float4* s1 = (const float4*)(wT + k0 * OTOT);
            float4* t1 = (float4*)smW;
#pragma unroll
            for (int r = 0; r < OTOT / 64; r++) t1[tid + 256 * r] = s1[tid + 256 * r];
        }
        __syncthreads();
#pragma unroll
        for (int kk = 0; kk < 16; kk++) {
            const float* ar = smW + kk * OTOT + o_base;
            const float* br = bufIn + (k0 + kk) * COLS + col_base;
            float b[6];
            float2 b01 = *(const float2*)(br);
            float2 b23 = *(const float2*)(br + 2);
            float2 b45 = *(const float2*)(br + 4);
            b[0] = b01.x; b[1] = b01.y; b[2] = b23.x; b[3] = b23.y; b[4] = b45.x; b[5] = b45.y;
            float af[8];
            *(float4*)&af[0] = *(const float4*)(ar);
            *(float4*)&af[4] = *(const float4*)(ar + 4);
#pragma unroll
            for (int oo = 0; oo < 8; oo++)
#pragma unroll
                for (int cc = 0; cc < 6; cc++)
                    acc[oo][cc] += af[oo] * b[cc];
        }
    }
}

// VN LeakyReLU (ns = 0): keep p where dot>=0 else p - dot/(dn+eps) * d. Tile = 8 ch x 2 points.
__device__ __forceinline__ void vn_combine(float accP[8][6], float accD[8][6])
{
#pragma unroll
    for (int oo = 0; oo < 8; oo++)
#pragma unroll
        for (int p = 0; p < 2; p++) {
            float p0 = accP[oo][3 * p], p1 = accP[oo][3 * p + 1], p2 = accP[oo][3 * p + 2];
            float q0 = accD[oo][3 * p], q1 = accD[oo][3 * p + 1], q2 = accD[oo][3 * p + 2];
            float dot = p0 * q0 + p1 * q1 + p2 * q2;
            float dn  = q0 * q0 + q1 * q1 + q2 * q2;
            if (dot < 0.f) {
                float s = dot / (dn + EPSV);
                accP[oo][3 * p]     = p0 - s * q0;
                accP[oo][3 * p + 1] = p1 - s * q1;
                accP[oo][3 * p + 2] = p2 - s * q2;
            }
        }
}

template<int COLS>
__device__ __forceinline__ void store_tile(float* buf, float acc[8][6], int o_base, int col_base)
{
#pragma unroll
    for (int oo = 0; oo < 8; oo++) {
        float* r = buf + (o_base + oo) * COLS + col_base;
#pragma unroll
        for (int cc = 0; cc < 6; cc++) r[cc] = acc[oo][cc];
    }
}

// ---------------------------------------------------------------------------
// setup kernels
// ---------------------------------------------------------------------------
__global__ void k_initkeys()
{
    int i = blockIdx.x * blockDim.x + threadIdx.x;
    if (i < NSEG * 128) d_key1[i] = 0ull;
    if (i < NSEG * 256) d_key2[i] = 0ull;
}

// W[o][c] (OxC) -> d_wt[dstOff + c*O + o]
__global__ void k_transpose(const float* __restrict__ src, int dstOff, int O, int C)
{
    __shared__ float t[32][33];
    int cb = blockIdx.x * 32, ob = blockIdx.y * 32;
    int x = threadIdx.x, y = threadIdx.y;
    for (int i = y; i < 32; i += 8) t[i][x] = src[(size_t)(ob + i) * C + cb + x];
    __syncthreads();
    for (int i = y; i < 32; i += 8) d_wt[dstOff + (size_t)(cb + i) * O + ob + x] = t[x][i];
}

// ---------------------------------------------------------------------------
// stage 1: vn1 -> vn2 -> vn3 -> (store g3, argmax over Wd1 dot)
// 32 points per CTA, 256 threads (16x16 map), smem = 2*[128][96] + 2*[16][128]
// ---------------------------------------------------------------------------
__global__ void __launch_bounds__(256, 1) k_stage1(const float* __restrict__ x,
                                                   const int* __restrict__ radius)
{
    extern __shared__ float sm[];
    float* bufA = sm;                 // [128][96]
    float* bufB = sm + 12288;         // [128][96]
    float* smW  = sm + 24576;         // 2 x [16][128]
    int tid = threadIdx.x;
    int n0 = blockIdx.x * 32;

    // load X tile transposed: bufA[c][p*3+j] = x[n0+p][c][j]
    const float* xg = x + (size_t)n0 * 384;
    for (int i4 = tid; i4 < 3072; i4 += 256) {
        float4 v = ((const float4*)xg)[i4];
        int lin = i4 * 4;
        int p = lin / 384, r = lin % 384;
        float vv[4] = {v.x, v.y, v.z, v.w};
#pragma unroll
        for (int e = 0; e < 4; e++) {
            int rr = r + e;
            int c = rr / 3, j = rr - c * 3;
            bufA[c * 96 + p * 3 + j] = vv[e];
        }
    }

    int ty = tid >> 4, tx = tid & 15;
    int o_base = ty * 8, col_base = tx * 6;

    float accP[8][6], accD[8][6];
#pragma unroll
    for (int oo = 0; oo < 8; oo++)
#pragma unroll
        for (int cc = 0; cc < 6; cc++) { accP[oo][cc] = 0.f; accD[oo][cc] = 0.f; }

    // L1: vn1
    mm_pair<128, 128, 96>(d_wt + O_W1F, d_wt + O_W1D, bufA, smW, accP, accD, o_base, col_base, tid);
    vn_combine(accP, accD);
    store_tile<96>(bufB, accP, o_base, col_base);

    // L2: vn2
#pragma unroll
    for (int oo = 0; oo < 8; oo++)
#pragma unroll
        for (int cc = 0; cc < 6; cc++) { accP[oo][cc] = 0.f; accD[oo][cc] = 0.f; }
    mm_pair<128, 128, 96>(d_wt + O_W2F, d_wt + O_W2D, bufB, smW, accP, accD, o_base, col_base, tid);
    vn_combine(accP, accD);
    store_tile<96>(bufA, accP, o_base, col_base);

    // L3: vn3 (Y kept in accP)
#pragma unroll
    for (int oo = 0; oo < 8; oo++)
#pragma unroll
        for (int cc = 0; cc < 6; cc++) accP[oo][cc] = 0.f;
    mm_one<128, 128, 96>(d_wt + O_W3, bufA, smW, accP, o_base, col_base, tid);
    store_tile<96>(bufB, accP, o_base, col_base);

    // write g3 to global scratch (layout [c][n*3+j])
#pragma unroll
    for (int oo = 0; oo < 8; oo++) {
        float* g = d_g3s + (size_t)(o_base + oo) * NT3 + (size_t)n0 * 3 + col_base;
#pragma unroll
        for (int cc = 0; cc < 6; cc++) g[cc] = accP[oo][cc];
    }

    // L3d: d = Wd1 * Y
#pragma unroll
    for (int oo = 0; oo < 8; oo++)
#pragma unroll
        for (int cc = 0; cc < 6; cc++) accD[oo][cc] = 0.f;
    mm_one<128, 128, 96>(d_wt + O_WD1, bufB, smW, accD, o_base, col_base, tid);

    // per-(channel,point) dot, argmax reduce across the CTA's 32 points
    int seg = radius[n0];
    unsigned int nA = (unsigned int)(n0 + 2 * tx);
#pragma unroll
    for (int oo = 0; oo < 8; oo++) {
        float dot0 = accP[oo][0] * accD[oo][0] + accP[oo][1] * accD[oo][1] + accP[oo][2] * accD[oo][2];
        float dot1 = accP[oo][3] * accD[oo][3] + accP[oo][4] * accD[oo][4] + accP[oo][5] * accD[oo][5];
        unsigned long long b0 = packkey(dot0, nA);
        unsigned long long b1 = packkey(dot1, nA + 1);
        unsigned long long best = (b0 > b1) ? b0 : b1;
#pragma unroll
        for (int m = 1; m < 16; m <<= 1) {
            unsigned long long o = shfl_xor_u64(best, m);
            if (o > best) best = o;
        }
        if (tx == 0) atomicMax(&d_key1[seg * 128 + o_base + oo], best);
    }
}

// ---------------------------------------------------------------------------
// gather + relu3  (one block per segment, 128 threads)
// ---------------------------------------------------------------------------
__global__ void k_relu3()
{
    __shared__ float G[128][3];
    int seg = blockIdx.x, c = threadIdx.x;
    unsigned long long key = d_key1[seg * 128 + c];
    unsigned int idx = 0xFFFFFFFFu - (unsigned int)(key & 0xFFFFFFFFull);
    if (idx >= NPTS) idx = 0;
    float g0 = d_g3s[(size_t)c * NT3 + (size_t)idx * 3 + 0];
    float g1 = d_g3s[(size_t)c * NT3 + (size_t)idx * 3 + 1];
    float g2 = d_g3s[(size_t)c * NT3 + (size_t)idx * 3 + 2];
    G[c][0] = g0; G[c][1] = g1; G[c][2] = g2;
    __syncthreads();
    float a0 = 0.f, a1 = 0.f, a2 = 0.f;
    const float* w = d_wt + O_WR3;   // k-major: w[k*128 + c]
    for (int k = 0; k < 128; k++) {
        float ww = w[k * 128 + c];
        a0 += ww * G[k][0]; a1 += ww * G[k][1]; a2 += ww * G[k][2];
    }
    float dot = g0 * a0 + g1 * a1 + g2 * a2;
    float dn  = a0 * a0 + a1 * a1 + a2 * a2;
    float o0 = g0, o1 = g1, o2 = g2;
    if (dot < 0.f) {
        float s = dot / (dn + EPSV);
        o0 -= s * a0; o1 -= s * a1; o2 -= s * a2;
    }
    d_r3[seg * 384 + c * 3 + 0] = o0;
    d_r3[seg * 384 + c * 3 + 1] = o1;
    d_r3[seg * 384 + c * 3 + 2] = o2;
}

// ---------------------------------------------------------------------------
// stage 2: concat -> vn4 -> vn5 -> (store h5, argmax over Wd2 dot)
// 16 points per CTA, 256 threads (32x8 map), smem = 2*[256][48] + 2*[16][256]
// ---------------------------------------------------------------------------
__global__ void __launch_bounds__(256, 1) k_stage2(const float* __restrict__ x,
                                                   const int* __restrict__ radius)
{
    extern __shared__ float sm[];
    float* bufA = sm;                 // [256][48]
    float* bufB = sm + 12288;         // [256][48]
    float* smW  = sm + 24576;         // 2 x [16][256]
    int tid = threadIdx.x;
    int n0 = blockIdx.x * 16;
    int seg = radius[n0];

    // x part: bufA[c][p*3+j] = x[n0+p][c][j], c < 128
    const float* xg = x + (size_t)n0 * 384;
    for (int i4 = tid; i4 < 1536; i4 += 256) {
        float4 v = ((const float4*)xg)[i4];
        int lin = i4 * 4;
        int p = lin / 384, r = lin % 384;
        float vv[4] = {v.x, v.y, v.z, v.w};
#pragma unroll
        for (int e = 0; e < 4; e++) {
            int rr = r + e;
            int c = rr / 3, j = rr - c * 3;
            bufA[c * 48 + p * 3 + j] = vv[e];
        }
    }
    // r3 broadcast part: bufA[128+c][p*3+j] = r3[seg][c][j]
    const float* r3s = d_r3 + seg * 384;
    for (int i = tid; i < 128 * 48; i += 256) {
        int c = i / 48, col = i - c * 48;
        int j = col % 3;
        bufA[(128 + c) * 48 + col] = r3s[c * 3 + j];
    }

    int ty = tid >> 3, tx = tid & 7;
    int o_base = ty * 8, col_base = tx * 6;

    float accP[8][6], accD[8][6];
#pragma unroll
    for (int oo = 0; oo < 8; oo++)
#pragma unroll
        for (int cc = 0; cc < 6; cc++) { accP[oo][cc] = 0.f; accD[oo][cc] = 0.f; }

    // L4: vn4
    mm_pair<256, 256, 48>(d_wt + O_W4F, d_wt + O_W4D, bufA, smW, accP, accD, o_base, col_base, tid);
    vn_combine(accP, accD);
    store_tile<48>(bufB, accP, o_base, col_base);

    // L5: vn5 (Y kept in accP)
#pragma unroll
    for (int oo = 0; oo < 8; oo++)
#pragma unroll
        for (int cc = 0; cc < 6; cc++) accP[oo][cc] = 0.f;
    mm_one<256, 256, 48>(d_wt + O_W5, bufB, smW, accP, o_base, col_base, tid);
    store_tile<48>(bufA, accP, o_base, col_base);

    // write h5 scratch (layout [c][n*3+j])
#pragma unroll
    for (int oo = 0; oo < 8; oo++) {
        float* g = d_h5s + (size_t)(o_base + oo) * NT3 + (size_t)n0 * 3 + col_base;
#pragma unroll
        for (int cc = 0; cc < 6; cc++) g[cc] = accP[oo][cc];
    }

    // L5d: d = Wd2 * Y
#pragma unroll
    for (int oo = 0; oo < 8; oo++)
#pragma unroll
        for (int cc = 0; cc < 6; cc++) accD[oo][cc] = 0.f;
    mm_one<256, 256, 48>(d_wt + O_WD2, bufA, smW, accD, o_base, col_base, tid);

    unsigned int nA = (unsigned int)(n0 + 2 * tx);
#pragma unroll
    for (int oo = 0; oo < 8; oo++) {
        float dot0 = accP[oo][0] * accD[oo][0] + accP[oo][1] * accD[oo][1] + accP[oo][2] * accD[oo][2];
        float dot1 = accP[oo][3] * accD[oo][3] + accP[oo][4] * accD[oo][4] + accP[oo][5] * accD[oo][5];
        unsigned long long b0 = packkey(dot0, nA);
        unsigned long long b1 = packkey(dot1, nA + 1);
        unsigned long long best = (b0 > b1) ? b0 : b1;
#pragma unroll
        for (int m = 1; m < 8; m <<= 1) {
            unsigned long long o = shfl_xor_u64(best, m);
            if (o > best) best = o;
        }
        if (tx == 0) atomicMax(&d_key2[seg * 256 + o_base + oo], best);
    }
}

// ---------------------------------------------------------------------------
// gather + relu5 -> output  (one block per segment, 256 threads)
// ---------------------------------------------------------------------------
__global__ void k_relu5(float* __restrict__ out)
{
    __shared__ float G[256][3];
    int seg = blockIdx.x, c = threadIdx.x;
    unsigned long long key = d_key2[seg * 256 + c];
    unsigned int idx = 0xFFFFFFFFu - (unsigned int)(key & 0xFFFFFFFFull);
    if (idx >= NPTS) idx = 0;
    float g0 = d_h5s[(size_t)c * NT3 + (size_t)idx * 3 + 0];
    float g1 = d_h5s[(size_t)c * NT3 + (size_t)idx * 3 + 1];
    float g2 = d_h5s[(size_t)c * NT3 + (size_t)idx * 3 + 2];
    G[c][0] = g0; G[c][1] = g1; G[c][2] = g2;
    __syncthreads();
    float a0 = 0.f, a1 = 0.f, a2 = 0.f;
    const float* w = d_wt + O_WR5;   // k-major: w[k*256 + c]
    for (int k = 0; k < 256; k++) {
        float ww = w[k * 256 + c];
        a0 += ww * G[k][0]; a1 += ww * G[k][1]; a2 += ww * G[k][2];
    }
    float dot = g0 * a0 + g1 * a1 + g2 * a2;
    float dn  = a0 * a0 + a1 * a1 + a2 * a2;
    float o0 = g0, o1 = g1, o2 = g2;
    if (dot < 0.f) {
        float s = dot / (dn + EPSV);
        o0 -= s * a0; o1 -= s * a1; o2 -= s * a2;
    }
    out[seg * 768 + c * 3 + 0] = o0;
    out[seg * 768 + c * 3 + 1] = o1;
    out[seg * 768 + c * 3 + 2] = o2;
}

// ---------------------------------------------------------------------------
// host launcher
// ---------------------------------------------------------------------------
extern "C" void kernel_launch(void* const* d_in, const int* in_sizes, int n_in,
                              void* d_out, int out_size)
{
    const float* x      = (const float*)d_in[0];
    const int*   radius = (const int*)d_in[1];
    const float* W1f = (const float*)d_in[2];
    const float* W1d = (const float*)d_in[3];
    const float* W2f = (const float*)d_in[4];
    const float* W2d = (const float*)d_in[5];
    const float* W3  = (const float*)d_in[6];
    const float* Wd1 = (const float*)d_in[7];
    const float* Wr3 = (const float*)d_in[8];
    const float* W4f = (const float*)d_in[9];
    const float* W4d = (const float*)d_in[10];
    const float* W5  = (const float*)d_in[11];
    const float* Wd2 = (const float*)d_in[12];
    const float* Wr5 = (const float*)d_in[13];

    cudaFuncSetAttribute(k_stage1, cudaFuncAttributeMaxDynamicSharedMemorySize, 114688);
    cudaFuncSetAttribute(k_stage2, cudaFuncAttributeMaxDynamicSharedMemorySize, 131072);

    k_initkeys<<<32, 256>>>();

    dim3 tb(32, 8);
    dim3 g128(4, 4), g256(8, 8);
    k_transpose<<<g128, tb>>>(W1f, O_W1F, 128, 128);
    k_transpose<<<g128, tb>>>(W1d, O_W1D, 128, 128);
    k_transpose<<<g128, tb>>>(W2f, O_W2F, 128, 128);
    k_transpose<<<g128, tb>>>(W2d, O_W2D, 128, 128);
    k_transpose<<<g128, tb>>>(W3,  O_W3,  128, 128);
    k_transpose<<<g128, tb>>>(Wd1, O_WD1, 128, 128);
    k_transpose<<<g128, tb>>>(Wr3, O_WR3, 128, 128);
    k_transpose<<<g256, tb>>>(W4f, O_W4F, 256, 256);
    k_transpose<<<g256, tb>>>(W4d, O_W4D, 256, 256);
    k_transpose<<<g256, tb>>>(W5,  O_W5,  256, 256);
    k_transpose<<<g256, tb>>>(Wd2, O_WD2, 256, 256);
    k_transpose<<<g256, tb>>>(Wr5, O_WR5, 256, 256);

    k_stage1<<<NPTS / 32, 256, 114688>>>(x, radius);
    k_relu3<<<NSEG, 128>>>();
    k_stage2<<<NPTS / 16, 256, 131072>>>(x, radius);
    k_relu5<<<NSEG, 256>>>((float*)d_out);
}

// round 3
// speedup vs baseline: 1.1433x; 1.1433x over previous
#include <cuda_runtime.h>

#define EPSV 1e-7f
#define NPTS 131072
#define NT3  393216        // NPTS*3
#define NSEG 32

// ---- transposed-weight offsets (in floats) within d_wt ----
#define O_W1F 0
#define O_W1D 16384
#define O_W2F 32768
#define O_W2D 49152
#define O_W3  65536
#define O_WD1 81920
#define O_WR3 98304
#define O_W4F 114688
#define O_W4D 180224
#define O_W5  245760
#define O_WD2 311296
#define O_WR5 376832
#define WT_TOTAL 442368

// ---- static device scratch (no allocations allowed) ----
__device__ float d_wt[WT_TOTAL];
__device__ float d_g3s[128ull * (unsigned long long)NT3];   // vn3 output, layout [c][n*3+j]
__device__ float d_h5s[256ull * (unsigned long long)NT3];   // vn5 output, layout [c][n*3+j]
__device__ float d_r3[NSEG * 128 * 3];                      // relu3 output per segment
__device__ unsigned long long d_key1[NSEG * 128];
__device__ unsigned long long d_key2[NSEG * 256];

typedef unsigned long long u64;

// ---------------------------------------------------------------------------
// helpers
// ---------------------------------------------------------------------------
__device__ __forceinline__ u64 packkey(float dot, unsigned int n) {
    unsigned int u = __float_as_uint(dot);
    u = (u & 0x80000000u) ? ~u : (u | 0x80000000u);   // order-preserving float->uint
    return ((u64)u << 32) | (u64)(0xFFFFFFFFu - n);   // tie -> min n
}

__device__ __forceinline__ u64 shfl_xor_u64(u64 v, int m) {
    unsigned int lo = (unsigned int)v;
    unsigned int hi = (unsigned int)(v >> 32);
    lo = __shfl_xor_sync(0xFFFFFFFFu, lo, m);
    hi = __shfl_xor_sync(0xFFFFFFFFu, hi, m);
    return ((u64)hi << 32) | lo;
}

// packed fp32x2 FMA: d = a * b + d (lanewise, round-to-nearest, exact fp32 per lane)
__device__ __forceinline__ void ffma2(u64& d, u64 a, u64 b) {
    asm("fma.rn.f32x2 %0, %1, %2, %0;" : "+l"(d) : "l"(a), "l"(b));
}
__device__ __forceinline__ u64 packdup(float x) {
    u64 r;
    asm("mov.b64 %0, {%1, %1};" : "=l"(r) : "r"(__float_as_uint(x)));
    return r;
}
__device__ __forceinline__ void unpack2(u64 v, float& lo, float& hi) {
    unsigned int l, h;
    asm("mov.b64 {%0, %1}, %2;" : "=r"(l), "=r"(h) : "l"(v));
    lo = __uint_as_float(l);
    hi = __uint_as_float(h);
}

// Y[o_pair, col] += W[o,k] * X[k,col], acc packed over output-row pairs.
// wT k-major: wT[k*OTOT + o]. smW: KT x OTOT tile (x2 for pair).
template<int K, int OTOT, int COLS, int KT>
__device__ __forceinline__ void mm_pair2(const float* __restrict__ wfT, const float* __restrict__ wdT,
                                         const float* __restrict__ bufIn, float* smW,
                                         u64 accP[4][6], u64 accD[4][6],
                                         int o_base, int col_base, int tid)
{
    float* smWd = smW + KT * OTOT;
    for (int k0 = 0; k0 < K; k0 += KT) {
        __syncthreads();
        {
            const float4* s1 = (const float4*)(wfT + k0 * OTOT);
            const float4* s2 = (const float4*)(wdT + k0 * OTOT);
            float4* t1 = (float4*)smW;
            float4* t2 = (float4*)smWd;
#pragma unroll
            for (int r = 0; r < KT * OTOT / 1024; r++) {
                t1[tid + 256 * r] = s1[tid + 256 * r];
                t2[tid + 256 * r] = s2[tid + 256 * r];
            }
        }
        __syncthreads();
#pragma unroll
        for (int kk = 0; kk < KT; kk++) {
            const u64* ar = (const u64*)(smW  + kk * OTOT + o_base);
            const u64* dr = (const u64*)(smWd + kk * OTOT + o_base);
            const float* br = bufIn + (k0 + kk) * COLS + col_base;
            float2 b01 = *(const float2*)(br);
            float2 b23 = *(const float2*)(br + 2);
            float2 b45 = *(const float2*)(br + 4);
            u64 b2[6];
            b2[0] = packdup(b01.x); b2[1] = packdup(b01.y);
            b2[2] = packdup(b23.x); b2[3] = packdup(b23.y);
            b2[4] = packdup(b45.x); b2[5] = packdup(b45.y);
            u64 a2f[4], a2d[4];
#pragma unroll
            for (int op = 0; op < 4; op++) { a2f[op] = ar[op]; a2d[op] = dr[op]; }
#pragma unroll
            for (int op = 0; op < 4; op++)
#pragma unroll
                for (int cc = 0; cc < 6; cc++) {
                    ffma2(accP[op][cc], a2f[op], b2[cc]);
                    ffma2(accD[op][cc], a2d[op], b2[cc]);
                }
        }
    }
}

template<int K, int OTOT, int COLS, int KT>
__device__ __forceinline__ void mm_one2(const float* __restrict__ wT,
                                        const float* __restrict__ bufIn, float* smW,
                                        u64 acc[4][6], int o_base, int col_base, int tid)
{
    for (int k0 = 0; k0 < K; k0 += KT) {
        __syncthreads();
        {
            const float4* s1 = (const float4*)(wT + k0 * OTOT);
            float4* t1 = (float4*)smW;
#pragma unroll
            for (int r = 0; r < KT * OTOT / 1024; r++) t1[tid + 256 * r] = s1[tid + 256 * r];
        }
        __syncthreads();
#pragma unroll
        for (int kk = 0; kk < KT; kk++) {
            const u64* ar = (const u64*)(smW + kk * OTOT + o_base);
            const float* br = bufIn + (k0 + kk) * COLS + col_base;
            float2 b01 = *(const float2*)(br);
            float2 b23 = *(const float2*)(br + 2);
            float2 b45 = *(const float2*)(br + 4);
            u64 b2[6];
            b2[0] = packdup(b01.x); b2[1] = packdup(b01.y);
            b2[2] = packdup(b23.x); b2[3] = packdup(b23.y);
            b2[4] = packdup(b45.x); b2[5] = packdup(b45.y);
            u64 a2[4];
#pragma unroll
            for (int op = 0; op < 4; op++) a2[op] = ar[op];
#pragma unroll
            for (int op = 0; op < 4; op++)
#pragma unroll
                for (int cc = 0; cc < 6; cc++)
                    ffma2(acc[op][cc], a2[op], b2[cc]);
        }
    }
}

__device__ __forceinline__ void zero_acc(u64 a[4][6]) {
#pragma unroll
    for (int op = 0; op < 4; op++)
#pragma unroll
        for (int cc = 0; cc < 6; cc++) a[op][cc] = 0ull;
}

__device__ __forceinline__ void unpack_acc(const u64 a[4][6], float f[8][6]) {
#pragma unroll
    for (int op = 0; op < 4; op++)
#pragma unroll
        for (int cc = 0; cc < 6; cc++)
            unpack2(a[op][cc], f[2 * op][cc], f[2 * op + 1][cc]);
}

// VN LeakyReLU (ns=0): keep p where dot>=0 else p - dot/(dn+eps)*d.
__device__ __forceinline__ void vn_combine(float accP[8][6], float accD[8][6])
{
#pragma unroll
    for (int oo = 0; oo < 8; oo++)
#pragma unroll
        for (int p = 0; p < 2; p++) {
            float p0 = accP[oo][3 * p], p1 = accP[oo][3 * p + 1], p2 = accP[oo][3 * p + 2];
            float q0 = accD[oo][3 * p], q1 = accD[oo][3 * p + 1], q2 = accD[oo][3 * p + 2];
            float dot = p0 * q0 + p1 * q1 + p2 * q2;
            float dn  = q0 * q0 + q1 * q1 + q2 * q2;
            if (dot < 0.f) {
                float s = dot / (dn + EPSV);
                accP[oo][3 * p]     = p0 - s * q0;
                accP[oo][3 * p + 1] = p1 - s * q1;
                accP[oo][3 * p + 2] = p2 - s * q2;
            }
        }
}

template<int COLS>
__device__ __forceinline__ void store_tile(float* buf, float acc[8][6], int o_base, int col_base)
{
#pragma unroll
    for (int oo = 0; oo < 8; oo++) {
        float* r = buf + (o_base + oo) * COLS + col_base;
#pragma unroll
        for (int cc = 0; cc < 6; cc++) r[cc] = acc[oo][cc];
    }
}

// ---------------------------------------------------------------------------
// setup kernels (batched so the launch sequence keeps stage2 at ncu's -s 5 slot)
// ---------------------------------------------------------------------------
__global__ void k_initkeys()
{
    int i = blockIdx.x * blockDim.x + threadIdx.x;
    if (i < NSEG * 128) d_key1[i] = 0ull;
    if (i < NSEG * 256) d_key2[i] = 0ull;
}

struct TList {
    const float* src[7];
    int off[7];
};

// W[o][c] (OxC) -> d_wt[off + c*O + o]; one matrix per blockIdx.z
__global__ void k_tmany(TList tl, int O, int C)
{
    __shared__ float t[32][33];
    const float* src = tl.src[blockIdx.z];
    int dstOff = tl.off[blockIdx.z];
    int cb = blockIdx.x * 32, ob = blockIdx.y * 32;
    int x = threadIdx.x, y = threadIdx.y;
    for (int i = y; i < 32; i += 8) t[i][x] = src[(size_t)(ob + i) * C + cb + x];
    __syncthreads();
    for (int i = y; i < 32; i += 8) d_wt[dstOff + (size_t)(cb + i) * O + ob + x] = t[x][i];
}

// ---------------------------------------------------------------------------
// stage 1: vn1 -> vn2 -> vn3 -> (store g3, argmax over Wd1 dot)
// 32 points per CTA, 256 threads (16x16 map), KT=32, smem = 2*[128][96] + 2*[32][128]
// ---------------------------------------------------------------------------
__global__ void __launch_bounds__(256, 1) k_stage1(const float* __restrict__ x,
                                                   const int* __restrict__ radius)
{
    extern __shared__ float sm[];
    float* bufA = sm;                 // [128][96]
    float* bufB = sm + 12288;         // [128][96]
    float* smW  = sm + 24576;         // 2 x [32][128]
    int tid = threadIdx.x;
    int n0 = blockIdx.x * 32;

    // load X tile transposed: bufA[c][p*3+j] = x[n0+p][c][j]
    const float* xg = x + (size_t)n0 * 384;
    for (int i4 = tid; i4 < 3072; i4 += 256) {
        float4 v = ((const float4*)xg)[i4];
        int lin = i4 * 4;
        int p = lin / 384, r = lin % 384;
        float vv[4] = {v.x, v.y, v.z, v.w};
#pragma unroll
        for (int e = 0; e < 4; e++) {
            int rr = r + e;
            int c = rr / 3, j = rr - c * 3;
            bufA[c * 96 + p * 3 + j] = vv[e];
        }
    }

    int ty = tid >> 4, tx = tid & 15;
    int o_base = ty * 8, col_base = tx * 6;

    u64 aP[4][6], aD[4][6];
    float fP[8][6], fD[8][6];

    // L1: vn1
    zero_acc(aP); zero_acc(aD);
    mm_pair2<128, 128, 96, 32>(d_wt + O_W1F, d_wt + O_W1D, bufA, smW, aP, aD, o_base, col_base, tid);
    unpack_acc(aP, fP); unpack_acc(aD, fD);
    vn_combine(fP, fD);
    store_tile<96>(bufB, fP, o_base, col_base);

    // L2: vn2
    zero_acc(aP); zero_acc(aD);
    mm_pair2<128, 128, 96, 32>(d_wt + O_W2F, d_wt + O_W2D, bufB, smW, aP, aD, o_base, col_base, tid);
    unpack_acc(aP, fP); unpack_acc(aD, fD);
    vn_combine(fP, fD);
    store_tile<96>(bufA, fP, o_base, col_base);

    // L3: vn3
    zero_acc(aP);
    mm_one2<128, 128, 96, 32>(d_wt + O_W3, bufA, smW, aP, o_base, col_base, tid);
    unpack_acc(aP, fP);
    store_tile<96>(bufB, fP, o_base, col_base);

    // write g3 to global scratch (layout [c][n*3+j])
#pragma unroll
    for (int oo = 0; oo < 8; oo++) {
        float* g = d_g3s + (size_t)(o_base + oo) * NT3 + (size_t)n0 * 3 + col_base;
#pragma unroll
        for (int cc = 0; cc < 6; cc++) g[cc] = fP[oo][cc];
    }

    // L3d: d = Wd1 * Y
    zero_acc(aD);
    mm_one2<128, 128, 96, 32>(d_wt + O_WD1, bufB, smW, aD, o_base, col_base, tid);
    unpack_acc(aD, fD);

    // per-(channel,point) dot, argmax reduce across the CTA's 32 points
    int seg = radius[n0];
    unsigned int nA = (unsigned int)(n0 + 2 * tx);
#pragma unroll
    for (int oo = 0; oo < 8; oo++) {
        float dot0 = fP[oo][0] * fD[oo][0] + fP[oo][1] * fD[oo][1] + fP[oo][2] * fD[oo][2];
        float dot1 = fP[oo][3] * fD[oo][3] + fP[oo][4] * fD[oo][4] + fP[oo][5] * fD[oo][5];
        u64 b0 = packkey(dot0, nA);
        u64 b1 = packkey(dot1, nA + 1);
        u64 best = (b0 > b1) ? b0 : b1;
#pragma unroll
        for (int m = 1; m < 16; m <<= 1) {
            u64 o = shfl_xor_u64(best, m);
            if (o > best) best = o;
        }
        if (tx == 0) atomicMax(&d_key1[seg * 128 + o_base + oo], best);
    }
}

// ---------------------------------------------------------------------------
// gather + relu3  (one block per segment, 128 threads)
// ---------------------------------------------------------------------------
__global__ void k_relu3()
{
    __shared__ float G[128][3];
    int seg = blockIdx.x, c = threadIdx.x;
    u64 key = d_key1[seg * 128 + c];
    unsigned int idx = 0xFFFFFFFFu - (unsigned int)(key & 0xFFFFFFFFull);
    if (idx >= NPTS) idx = 0;
    float g0 = d_g3s[(size_t)c * NT3 + (size_t)idx * 3 + 0];
    float g1 = d_g3s[(size_t)c * NT3 + (size_t)idx * 3 + 1];
    float g2 = d_g3s[(size_t)c * NT3 + (size_t)idx * 3 + 2];
    G[c][0] = g0; G[c][1] = g1; G[c][2] = g2;
    __syncthreads();
    float a0 = 0.f, a1 = 0.f, a2 = 0.f;
    const float* w = d_wt + O_WR3;   // k-major: w[k*128 + c]
    for (int k = 0; k < 128; k++) {
        float ww = w[k * 128 + c];
        a0 += ww * G[k][0]; a1 += ww * G[k][1]; a2 += ww * G[k][2];
    }
    float dot = g0 * a0 + g1 * a1 + g2 * a2;
    float dn  = a0 * a0 + a1 * a1 + a2 * a2;
    float o0 = g0, o1 = g1, o2 = g2;
    if (dot < 0.f) {
        float s = dot / (dn + EPSV);
        o0 -= s * a0; o1 -= s * a1; o2 -= s * a2;
    }
    d_r3[seg * 384 + c * 3 + 0] = o0;
    d_r3[seg * 384 + c * 3 + 1] = o1;
    d_r3[seg * 384 + c * 3 + 2] = o2;
}

// ---------------------------------------------------------------------------
// stage 2: concat -> vn4 -> vn5 -> (store h5, argmax over Wd2 dot)
// 16 points per CTA, 256 threads (32x8 map), KT=32, smem = 2*[256][48] + 2*[32][256]
// ---------------------------------------------------------------------------
__global__ void __launch_bounds__(256, 1) k_stage2(const float* __restrict__ x,
                                                   const int* __restrict__ radius)
{
    extern __shared__ float sm[];
    float* bufA = sm;                 // [256][48]
    float* bufB = sm + 12288;         // [256][48]
    float* smW  = sm + 24576;         // 2 x [32][256]
    int tid = threadIdx.x;
    int n0 = blockIdx.x * 16;
    int seg = radius[n0];

    // x part: bufA[c][p*3+j] = x[n0+p][c][j], c < 128
    const float* xg = x + (size_t)n0 * 384;
    for (int i4 = tid; i4 < 1536; i4 += 256) {
        float4 v = ((const float4*)xg)[i4];
        int lin = i4 * 4;
        int p = lin / 384, r = lin % 384;
        float vv[4] = {v.x, v.y, v.z, v.w};
#pragma unroll
        for (int e = 0; e < 4; e++) {
            int rr = r + e;
            int c = rr / 3, j = rr - c * 3;
            bufA[c * 48 + p * 3 + j] = vv[e];
        }
    }
    // r3 broadcast part: bufA[128+c][p*3+j] = r3[seg][c][j]
    const float* r3s = d_r3 + seg * 384;
    for (int i = tid; i < 128 * 48; i += 256) {
        int c = i / 48, col = i - c * 48;
        int j = col % 3;
        bufA[(128 + c) * 48 + col] = r3s[c * 3 + j];
    }

    int ty = tid >> 3, tx = tid & 7;
    int o_base = ty * 8, col_base = tx * 6;

    u64 aP[4][6], aD[4][6];
    float fP[8][6], fD[8][6];

    // L4: vn4
    zero_acc(aP); zero_acc(aD);
    mm_pair2<256, 256, 48, 32>(d_wt + O_W4F, d_wt + O_W4D, bufA, smW, aP, aD, o_base, col_base, tid);
    unpack_acc(aP, fP); unpack_acc(aD, fD);
    vn_combine(fP, fD);
    store_tile<48>(bufB, fP, o_base, col_base);

    // L5: vn5
    zero_acc(aP);
    mm_one2<256, 256, 48, 32>(d_wt + O_W5, bufB, smW, aP, o_base, col_base, tid);
    unpack_acc(aP, fP);
    store_tile<48>(bufA, fP, o_base, col_base);

    // write h5 scratch (layout [c][n*3+j])
#pragma unroll
    for (int oo = 0; oo < 8; oo++) {
        float* g = d_h5s + (size_t)(o_base + oo) * NT3 + (size_t)n0 * 3 + col_base;
#pragma unroll
        for (int cc = 0; cc < 6; cc++) g[cc] = fP[oo][cc];
    }

    // L5d: d = Wd2 * Y
    zero_acc(aD);
    mm_one2<256, 256, 48, 32>(d_wt + O_WD2, bufA, smW, aD, o_base, col_base, tid);
    unpack_acc(aD, fD);

    unsigned int nA = (unsigned int)(n0 + 2 * tx);
#pragma unroll
    for (int oo = 0; oo < 8; oo++) {
        float dot0 = fP[oo][0] * fD[oo][0] + fP[oo][1] * fD[oo][1] + fP[oo][2] * fD[oo][2];
        float dot1 = fP[oo][3] * fD[oo][3] + fP[oo][4] * fD[oo][4] + fP[oo][5] * fD[oo][5];
        u64 b0 = packkey(dot0, nA);
        u64 b1 = packkey(dot1, nA + 1);
        u64 best = (b0 > b1) ? b0 : b1;
#pragma unroll
        for (int m = 1; m < 8; m <<= 1) {
            u64 o = shfl_xor_u64(best, m);
            if (o > best) best = o;
        }
        if (tx == 0) atomicMax(&d_key2[seg * 256 + o_base + oo], best);
    }
}

// ---------------------------------------------------------------------------
// gather + relu5 -> output  (one block per segment, 256 threads)
// ---------------------------------------------------------------------------
__global__ void k_relu5(float* __restrict__ out)
{
    __shared__ float G[256][3];
    int seg = blockIdx.x, c = threadIdx.x;
    u64 key = d_key2[seg * 256 + c];
    unsigned int idx = 0xFFFFFFFFu - (unsigned int)(key & 0xFFFFFFFFull);
    if (idx >= NPTS) idx = 0;
    float g0 = d_h5s[(size_t)c * NT3 + (size_t)idx * 3 + 0];
    float g1 = d_h5s[(size_t)c * NT3 + (size_t)idx * 3 + 1];
    float g2 = d_h5s[(size_t)c * NT3 + (size_t)idx * 3 + 2];
    G[c][0] = g0; G[c][1] = g1; G[c][2] = g2;
    __syncthreads();
    float a0 = 0.f, a1 = 0.f, a2 = 0.f;
    const float* w = d_wt + O_WR5;   // k-major: w[k*256 + c]
    for (int k = 0; k < 256; k++) {
        float ww = w[k * 256 + c];
        a0 += ww * G[k][0]; a1 += ww * G[k][1]; a2 += ww * G[k][2];
    }
    float dot = g0 * a0 + g1 * a1 + g2 * a2;
    float dn  = a0 * a0 + a1 * a1 + a2 * a2;
    float o0 = g0, o1 = g1, o2 = g2;
    if (dot < 0.f) {
        float s = dot / (dn + EPSV);
        o0 -= s * a0; o1 -= s * a1; o2 -= s * a2;
    }
    out[seg * 768 + c * 3 + 0] = o0;
    out[seg * 768 + c * 3 + 1] = o1;
    out[seg * 768 + c * 3 + 2] = o2;
}

// ---------------------------------------------------------------------------
// host launcher
// Launch order (6 per call): initkeys, t128, t256, stage1, relu3, stage2, relu5
//   -> ncu -s 5 -c 1 lands on k_stage2 (the dominant kernel)
// ---------------------------------------------------------------------------
extern "C" void kernel_launch(void* const* d_in, const int* in_sizes, int n_in,
                              void* d_out, int out_size)
{
    const float* x      = (const float*)d_in[0];
    const int*   radius = (const int*)d_in[1];

    cudaFuncSetAttribute(k_stage1, cudaFuncAttributeMaxDynamicSharedMemorySize, 131072);
    cudaFuncSetAttribute(k_stage2, cudaFuncAttributeMaxDynamicSharedMemorySize, 163840);

    k_initkeys<<<32, 256>>>();

    dim3 tb(32, 8);
    TList t128;
    t128.src[0] = (const float*)d_in[2];  t128.off[0] = O_W1F;
    t128.src[1] = (const float*)d_in[3];  t128.off[1] = O_W1D;
    t128.src[2] = (const float*)d_in[4];  t128.off[2] = O_W2F;
    t128.src[3] = (const float*)d_in[5];  t128.off[3] = O_W2D;
    t128.src[4] = (const float*)d_in[6];  t128.off[4] = O_W3;
    t128.src[5] = (const float*)d_in[7];  t128.off[5] = O_WD1;
    t128.src[6] = (const float*)d_in[8];  t128.off[6] = O_WR3;
    k_tmany<<<dim3(4, 4, 7), tb>>>(t128, 128, 128);

    TList t256;
    t256.src[0] = (const float*)d_in[9];   t256.off[0] = O_W4F;
    t256.src[1] = (const float*)d_in[10];  t256.off[1] = O_W4D;
    t256.src[2] = (const float*)d_in[11];  t256.off[2] = O_W5;
    t256.src[3] = (const float*)d_in[12];  t256.off[3] = O_WD2;
    t256.src[4] = (const float*)d_in[13];  t256.off[4] = O_WR5;
    t256.src[5] = t256.src[4];             t256.off[5] = O_WR5;  // unused (grid.z=5)
    t256.src[6] = t256.src[4];             t256.off[6] = O_WR5;
    k_tmany<<<dim3(8, 8, 5), tb>>>(t256, 256, 256);

    k_stage1<<<NPTS / 32, 256, 131072>>>(x, radius);
    k_relu3<<<NSEG, 128>>>();
    k_stage2<<<NPTS / 16, 256, 163840>>>(x, radius);
    k_relu5<<<NSEG, 256>>>((float*)d_out);
}

// round 4
// speedup vs baseline: 1.2313x; 1.0770x over previous
#include <cuda_runtime.h>

#define EPSV 1e-7f
#define NPTS 131072
#define NT3  393216        // NPTS*3
#define NSEG 32

// ---- transposed-weight offsets (in floats) within d_wt ----
#define O_W1F 0
#define O_W1D 16384
#define O_W2F 32768
#define O_W2D 49152
#define O_W3  65536
#define O_WD1 81920
#define O_WR3 98304
#define O_W4F 114688
#define O_W4D 180224
#define O_W5  245760
#define O_WD2 311296
#define O_WR5 376832
#define WT_TOTAL 442368

// ---- static device scratch (no allocations allowed) ----
__device__ float d_wt[WT_TOTAL];
__device__ float d_g3s[128ull * (unsigned long long)NT3];   // vn3 output, layout [c][n*3+j]
__device__ float d_h5s[256ull * (unsigned long long)NT3];   // vn5 output, layout [c][n*3+j]
__device__ float d_r3[NSEG * 128 * 3];                      // relu3 output per segment
__device__ unsigned long long d_key1[NSEG * 128];
__device__ unsigned long long d_key2[NSEG * 256];

typedef unsigned long long u64;

// ---------------------------------------------------------------------------
// helpers
// ---------------------------------------------------------------------------
__device__ __forceinline__ u64 packkey(float dot, unsigned int n) {
    unsigned int u = __float_as_uint(dot);
    u = (u & 0x80000000u) ? ~u : (u | 0x80000000u);   // order-preserving float->uint
    return ((u64)u << 32) | (u64)(0xFFFFFFFFu - n);   // tie -> min n
}

__device__ __forceinline__ u64 shfl_xor_u64(u64 v, int m) {
    unsigned int lo = (unsigned int)v;
    unsigned int hi = (unsigned int)(v >> 32);
    lo = __shfl_xor_sync(0xFFFFFFFFu, lo, m);
    hi = __shfl_xor_sync(0xFFFFFFFFu, hi, m);
    return ((u64)hi << 32) | lo;
}

// packed fp32x2 FMA: d = a * b + d (lanewise, exact fp32 per lane)
__device__ __forceinline__ void ffma2(u64& d, u64 a, u64 b) {
    asm("fma.rn.f32x2 %0, %1, %2, %0;" : "+l"(d) : "l"(a), "l"(b));
}
__device__ __forceinline__ u64 packdup(float x) {
    u64 r;
    asm("mov.b64 %0, {%1, %1};" : "=l"(r) : "r"(__float_as_uint(x)));
    return r;
}
__device__ __forceinline__ void unpack2(u64 v, float& lo, float& hi) {
    unsigned int l, h;
    asm("mov.b64 {%0, %1}, %2;" : "=r"(l), "=r"(h) : "l"(v));
    lo = __uint_as_float(l);
    hi = __uint_as_float(h);
}

// cp.async 16B helpers
__device__ __forceinline__ void cpa16(float* smdst, const float4* gsrc) {
    unsigned s = (unsigned)__cvta_generic_to_shared(smdst);
    asm volatile("cp.async.cg.shared.global [%0], [%1], 16;" :: "r"(s), "l"(gsrc));
}
__device__ __forceinline__ void cp_commit() { asm volatile("cp.async.commit_group;"); }
__device__ __forceinline__ void cp_wait1() { asm volatile("cp.async.wait_group 1;" ::: "memory"); }
__device__ __forceinline__ void cp_wait0() { asm volatile("cp.async.wait_group 0;" ::: "memory"); }

// ---------------------------------------------------------------------------
// matmul cores: Y[o_pair, col] += W[o,k] * X[k,col], acc packed over output pairs.
// wT k-major: wT[k*OTOT + o]. smW: double-buffered cp.async weight staging.
// Region size needed in smW: 4*KT*OTOT floats (pair) — mm_one uses half of it.
// ---------------------------------------------------------------------------
template<int K, int OTOT, int COLS, int KT>
__device__ __forceinline__ void mm_pair2(const float* __restrict__ wfT, const float* __restrict__ wdT,
                                         const float* __restrict__ bufIn, float* smW,
                                         u64 accP[4][6], u64 accD[4][6],
                                         int o_base, int col_base, int tid)
{
    constexpr int TW    = KT * OTOT;   // floats per matrix tile
    constexpr int BUFSZ = 2 * TW;      // floats per double-buffer slot (f+d)
    constexpr int NT    = K / KT;
    constexpr int PER   = TW / 4 / 256;

    // issue tile t into slot b
    {
        float* df = smW;
        float* dd = smW + TW;
        const float4* sf = (const float4*)(wfT);
        const float4* sd = (const float4*)(wdT);
#pragma unroll
        for (int r = 0; r < PER; r++) {
            cpa16(df + (tid + 256 * r) * 4, sf + tid + 256 * r);
            cpa16(dd + (tid + 256 * r) * 4, sd + tid + 256 * r);
        }
        cp_commit();
    }
    for (int t = 0; t < NT; t++) {
        if (t + 1 < NT) {
            float* df = smW + ((t + 1) & 1) * BUFSZ;
            float* dd = df + TW;
            const float4* sf = (const float4*)(wfT + (t + 1) * KT * OTOT);
            const float4* sd = (const float4*)(wdT + (t + 1) * KT * OTOT);
#pragma unroll
            for (int r = 0; r < PER; r++) {
                cpa16(df + (tid + 256 * r) * 4, sf + tid + 256 * r);
                cpa16(dd + (tid + 256 * r) * 4, sd + tid + 256 * r);
            }
            cp_commit();
            cp_wait1();
        } else {
            cp_wait0();
        }
        __syncthreads();
        const float* Wf = smW + (t & 1) * BUFSZ;
        const float* Wd = Wf + TW;
#pragma unroll
        for (int kk = 0; kk < KT; kk++) {
            const ulonglong2* ar = (const ulonglong2*)(Wf + kk * OTOT + o_base);
            const ulonglong2* dr = (const ulonglong2*)(Wd + kk * OTOT + o_base);
            const float* br = bufIn + (t * KT + kk) * COLS + col_base;
            float2 b01 = *(const float2*)(br);
            float2 b23 = *(const float2*)(br + 2);
            float2 b45 = *(const float2*)(br + 4);
            u64 b2[6];
            b2[0] = packdup(b01.x); b2[1] = packdup(b01.y);
            b2[2] = packdup(b23.x); b2[3] = packdup(b23.y);
            b2[4] = packdup(b45.x); b2[5] = packdup(b45.y);
            ulonglong2 af0 = ar[0], af1 = ar[1], ad0 = dr[0], ad1 = dr[1];
            u64 a2f[4] = {af0.x, af0.y, af1.x, af1.y};
            u64 a2d[4] = {ad0.x, ad0.y, ad1.x, ad1.y};
#pragma unroll
            for (int op = 0; op < 4; op++)
#pragma unroll
                for (int cc = 0; cc < 6; cc++) {
                    ffma2(accP[op][cc], a2f[op], b2[cc]);
                    ffma2(accD[op][cc], a2d[op], b2[cc]);
                }
        }
        __syncthreads();
    }
}

template<int K, int OTOT, int COLS, int KT>
__device__ __forceinline__ void mm_one2(const float* __restrict__ wT,
                                        const float* __restrict__ bufIn, float* smW,
                                        u64 acc[4][6], int o_base, int col_base, int tid)
{
    constexpr int TW  = KT * OTOT;
    constexpr int NT  = K / KT;
    constexpr int PER = TW / 4 / 256;

    {
        const float4* sf = (const float4*)(wT);
#pragma unroll
        for (int r = 0; r < PER; r++)
            cpa16(smW + (tid + 256 * r) * 4, sf + tid + 256 * r);
        cp_commit();
    }
    for (int t = 0; t < NT; t++) {
        if (t + 1 < NT) {
            float* df = smW + ((t + 1) & 1) * TW;
            const float4* sf = (const float4*)(wT + (t + 1) * KT * OTOT);
#pragma unroll
            for (int r = 0; r < PER; r++)
                cpa16(df + (tid + 256 * r) * 4, sf + tid + 256 * r);
            cp_commit();
            cp_wait1();
        } else {
            cp_wait0();
        }
        __syncthreads();
        const float* Wf = smW + (t & 1) * TW;
#pragma unroll
        for (int kk = 0; kk < KT; kk++) {
            const ulonglong2* ar = (const ulonglong2*)(Wf + kk * OTOT + o_base);
            const float* br = bufIn + (t * KT + kk) * COLS + col_base;
            float2 b01 = *(const float2*)(br);
            float2 b23 = *(const float2*)(br + 2);
            float2 b45 = *(const float2*)(br + 4);
            u64 b2[6];
            b2[0] = packdup(b01.x); b2[1] = packdup(b01.y);
            b2[2] = packdup(b23.x); b2[3] = packdup(b23.y);
            b2[4] = packdup(b45.x); b2[5] = packdup(b45.y);
            ulonglong2 af0 = ar[0], af1 = ar[1];
            u64 a2[4] = {af0.x, af0.y, af1.x, af1.y};
#pragma unroll
            for (int op = 0; op < 4; op++)
#pragma unroll
                for (int cc = 0; cc < 6; cc++)
                    ffma2(acc[op][cc], a2[op], b2[cc]);
        }
        __syncthreads();
    }
}

__device__ __forceinline__ void zero_acc(u64 a[4][6]) {
#pragma unroll
    for (int op = 0; op < 4; op++)
#pragma unroll
        for (int cc = 0; cc < 6; cc++) a[op][cc] = 0ull;
}

__device__ __forceinline__ void unpack_acc(const u64 a[4][6], float f[8][6]) {
#pragma unroll
    for (int op = 0; op < 4; op++)
#pragma unroll
        for (int cc = 0; cc < 6; cc++)
            unpack2(a[op][cc], f[2 * op][cc], f[2 * op + 1][cc]);
}

// VN LeakyReLU (ns=0): keep p where dot>=0 else p - dot/(dn+eps)*d.
__device__ __forceinline__ void vn_combine(float accP[8][6], float accD[8][6])
{
#pragma unroll
    for (int oo = 0; oo < 8; oo++)
#pragma unroll
        for (int p = 0; p < 2; p++) {
            float p0 = accP[oo][3 * p], p1 = accP[oo][3 * p + 1], p2 = accP[oo][3 * p + 2];
            float q0 = accD[oo][3 * p], q1 = accD[oo][3 * p + 1], q2 = accD[oo][3 * p + 2];
            float dot = p0 * q0 + p1 * q1 + p2 * q2;
            float dn  = q0 * q0 + q1 * q1 + q2 * q2;
            if (dot < 0.f) {
                float s = dot / (dn + EPSV);
                accP[oo][3 * p]     = p0 - s * q0;
                accP[oo][3 * p + 1] = p1 - s * q1;
                accP[oo][3 * p + 2] = p2 - s * q2;
            }
        }
}

template<int COLS>
__device__ __forceinline__ void store_tile(float* buf, float acc[8][6], int o_base, int col_base)
{
#pragma unroll
    for (int oo = 0; oo < 8; oo++) {
        float* r = buf + (o_base + oo) * COLS + col_base;
#pragma unroll
        for (int cc = 0; cc < 6; cc++) r[cc] = acc[oo][cc];
    }
}

// ---------------------------------------------------------------------------
// setup kernels
// ---------------------------------------------------------------------------
__global__ void k_initkeys()
{
    int i = blockIdx.x * blockDim.x + threadIdx.x;
    if (i < NSEG * 128) d_key1[i] = 0ull;
    if (i < NSEG * 256) d_key2[i] = 0ull;
}

struct TList {
    const float* src[7];
    int off[7];
};

// W[o][c] (OxC) -> d_wt[off + c*O + o]; one matrix per blockIdx.z
__global__ void k_tmany(TList tl, int O, int C)
{
    __shared__ float t[32][33];
    const float* src = tl.src[blockIdx.z];
    int dstOff = tl.off[blockIdx.z];
    int cb = blockIdx.x * 32, ob = blockIdx.y * 32;
    int x = threadIdx.x, y = threadIdx.y;
    for (int i = y; i < 32; i += 8) t[i][x] = src[(size_t)(ob + i) * C + cb + x];
    __syncthreads();
    for (int i = y; i < 32; i += 8) d_wt[dstOff + (size_t)(cb + i) * O + ob + x] = t[x][i];
}

// ---------------------------------------------------------------------------
// stage 1: vn1 -> vn2 -> vn3 -> (store g3, argmax over Wd1 dot)
// 32 points per CTA, 256 threads (16x16 map), KT=32
// smem: buf [128][96] (48KB, in-place reused) + smW 4*32*128 floats (64KB) = 112KB
// ---------------------------------------------------------------------------
__global__ void __launch_bounds__(256, 1) k_stage1(const float* __restrict__ x,
                                                   const int* __restrict__ radius)
{
    extern __shared__ float sm[];
    float* bufA = sm;                 // [128][96]
    float* smW  = sm + 12288;         // 4 x [32][128] (double-buffered f+d)
    int tid = threadIdx.x;
    int n0 = blockIdx.x * 32;

    // load X tile transposed: bufA[c][p*3+j] = x[n0+p][c][j]
    const float* xg = x + (size_t)n0 * 384;
    for (int i4 = tid; i4 < 3072; i4 += 256) {
        float4 v = ((const float4*)xg)[i4];
        int lin = i4 * 4;
        int p = lin / 384, r = lin % 384;
        float vv[4] = {v.x, v.y, v.z, v.w};
#pragma unroll
        for (int e = 0; e < 4; e++) {
            int rr = r + e;
            int c = rr / 3, j = rr - c * 3;
            bufA[c * 96 + p * 3 + j] = vv[e];
        }
    }

    int ty = tid >> 4, tx = tid & 15;
    int o_base = ty * 8, col_base = tx * 6;

    u64 aP[4][6], aD[4][6];
    float fP[8][6], fD[8][6];

    // L1: vn1  (mm ends with a barrier -> safe to overwrite bufA)
    zero_acc(aP); zero_acc(aD);
    mm_pair2<128, 128, 96, 32>(d_wt + O_W1F, d_wt + O_W1D, bufA, smW, aP, aD, o_base, col_base, tid);
    unpack_acc(aP, fP); unpack_acc(aD, fD);
    vn_combine(fP, fD);
    store_tile<96>(bufA, fP, o_base, col_base);

    // L2: vn2
    zero_acc(aP); zero_acc(aD);
    mm_pair2<128, 128, 96, 32>(d_wt + O_W2F, d_wt + O_W2D, bufA, smW, aP, aD, o_base, col_base, tid);
    unpack_acc(aP, fP); unpack_acc(aD, fD);
    vn_combine(fP, fD);
    store_tile<96>(bufA, fP, o_base, col_base);

    // L3: vn3
    zero_acc(aP);
    mm_one2<128, 128, 96, 32>(d_wt + O_W3, bufA, smW, aP, o_base, col_base, tid);
    unpack_acc(aP, fP);
    store_tile<96>(bufA, fP, o_base, col_base);

    // write g3 to global scratch (layout [c][n*3+j])
#pragma unroll
    for (int oo = 0; oo < 8; oo++) {
        float* g = d_g3s + (size_t)(o_base + oo) * NT3 + (size_t)n0 * 3 + col_base;
#pragma unroll
        for (int cc = 0; cc < 6; cc++) g[cc] = fP[oo][cc];
    }

    // L3d: d = Wd1 * Y   (bufA holds Y)
    zero_acc(aD);
    mm_one2<128, 128, 96, 32>(d_wt + O_WD1, bufA, smW, aD, o_base, col_base, tid);
    unpack_acc(aD, fD);

    // per-(channel,point) dot, argmax reduce across the CTA's 32 points
    int seg = radius[n0];
    unsigned int nA = (unsigned int)(n0 + 2 * tx);
#pragma unroll
    for (int oo = 0; oo < 8; oo++) {
        float dot0 = fP[oo][0] * fD[oo][0] + fP[oo][1] * fD[oo][1] + fP[oo][2] * fD[oo][2];
        float dot1 = fP[oo][3] * fD[oo][3] + fP[oo][4] * fD[oo][4] + fP[oo][5] * fD[oo][5];
        u64 b0 = packkey(dot0, nA);
        u64 b1 = packkey(dot1, nA + 1);
        u64 best = (b0 > b1) ? b0 : b1;
#pragma unroll
        for (int m = 1; m < 16; m <<= 1) {
            u64 o = shfl_xor_u64(best, m);
            if (o > best) best = o;
        }
        if (tx == 0) atomicMax(&d_key1[seg * 128 + o_base + oo], best);
    }
}

// ---------------------------------------------------------------------------
// gather + relu3  (one block per segment, 128 threads)
// ---------------------------------------------------------------------------
__global__ void k_relu3()
{
    __shared__ float G[128][3];
    int seg = blockIdx.x, c = threadIdx.x;
    u64 key = d_key1[seg * 128 + c];
    unsigned int idx = 0xFFFFFFFFu - (unsigned int)(key & 0xFFFFFFFFull);
    if (idx >= NPTS) idx = 0;
    float g0 = d_g3s[(size_t)c * NT3 + (size_t)idx * 3 + 0];
    float g1 = d_g3s[(size_t)c * NT3 + (size_t)idx * 3 + 1];
    float g2 = d_g3s[(size_t)c * NT3 + (size_t)idx * 3 + 2];
    G[c][0] = g0; G[c][1] = g1; G[c][2] = g2;
    __syncthreads();
    float a0 = 0.f, a1 = 0.f, a2 = 0.f;
    const float* w = d_wt + O_WR3;   // k-major: w[k*128 + c]
    for (int k = 0; k < 128; k++) {
        float ww = w[k * 128 + c];
        a0 += ww * G[k][0]; a1 += ww * G[k][1]; a2 += ww * G[k][2];
    }
    float dot = g0 * a0 + g1 * a1 + g2 * a2;
    float dn  = a0 * a0 + a1 * a1 + a2 * a2;
    float o0 = g0, o1 = g1, o2 = g2;
    if (dot < 0.f) {
        float s = dot / (dn + EPSV);
        o0 -= s * a0; o1 -= s * a1; o2 -= s * a2;
    }
    d_r3[seg * 384 + c * 3 + 0] = o0;
    d_r3[seg * 384 + c * 3 + 1] = o1;
    d_r3[seg * 384 + c * 3 + 2] = o2;
}

// ---------------------------------------------------------------------------
// stage 2: concat -> vn4 -> vn5 -> (store h5, argmax over Wd2 dot)
// 16 points per CTA, 256 threads (32x8 map), KT=32
// smem: buf [256][48] (48KB, in-place) + smW 4*32*256 floats (128KB) = 176KB
// ---------------------------------------------------------------------------
__global__ void __launch_bounds__(256, 1) k_stage2(const float* __restrict__ x,
                                                   const int* __restrict__ radius)
{
    extern __shared__ float sm[];
    float* bufA = sm;                 // [256][48]
    float* smW  = sm + 12288;         // 4 x [32][256]
    int tid = threadIdx.x;
    int n0 = blockIdx.x * 16;
    int seg = radius[n0];

    // x part: bufA[c][p*3+j] = x[n0+p][c][j], c < 128
    const float* xg = x + (size_t)n0 * 384;
    for (int i4 = tid; i4 < 1536; i4 += 256) {
        float4 v = ((const float4*)xg)[i4];
        int lin = i4 * 4;
        int p = lin / 384, r = lin % 384;
        float vv[4] = {v.x, v.y, v.z, v.w};
#pragma unroll
        for (int e = 0; e < 4; e++) {
            int rr = r + e;
            int c = rr / 3, j = rr - c * 3;
            bufA[c * 48 + p * 3 + j] = vv[e];
        }
    }
    // r3 broadcast part: bufA[128+c][p*3+j] = r3[seg][c][j]
    const float* r3s = d_r3 + seg * 384;
    for (int i = tid; i < 128 * 48; i += 256) {
        int c = i / 48, col = i - c * 48;
        int j = col % 3;
        bufA[(128 + c) * 48 + col] = r3s[c * 3 + j];
    }

    int ty = tid >> 3, tx = tid & 7;
    int o_base = ty * 8, col_base = tx * 6;

    u64 aP[4][6], aD[4][6];
    float fP[8][6], fD[8][6];

    // L4: vn4
    zero_acc(aP); zero_acc(aD);
    mm_pair2<256, 256, 48, 32>(d_wt + O_W4F, d_wt + O_W4D, bufA, smW, aP, aD, o_base, col_base, tid);
    unpack_acc(aP, fP); unpack_acc(aD, fD);
    vn_combine(fP, fD);
    store_tile<48>(bufA, fP, o_base, col_base);

    // L5: vn5
    zero_acc(aP);
    mm_one2<256, 256, 48, 32>(d_wt + O_W5, bufA, smW, aP, o_base, col_base, tid);
    unpack_acc(aP, fP);
    store_tile<48>(bufA, fP, o_base, col_base);

    // write h5 scratch (layout [c][n*3+j])
#pragma unroll
    for (int oo = 0; oo < 8; oo++) {
        float* g = d_h5s + (size_t)(o_base + oo) * NT3 + (size_t)n0 * 3 + col_base;
#pragma unroll
        for (int cc = 0; cc < 6; cc++) g[cc] = fP[oo][cc];
    }

    // L5d: d = Wd2 * Y   (bufA holds Y)
    zero_acc(aD);
    mm_one2<256, 256, 48, 32>(d_wt + O_WD2, bufA, smW, aD, o_base, col_base, tid);
    unpack_acc(aD, fD);

    unsigned int nA = (unsigned int)(n0 + 2 * tx);
#pragma unroll
    for (int oo = 0; oo < 8; oo++) {
        float dot0 = fP[oo][0] * fD[oo][0] + fP[oo][1] * fD[oo][1] + fP[oo][2] * fD[oo][2];
        float dot1 = fP[oo][3] * fD[oo][3] + fP[oo][4] * fD[oo][4] + fP[oo][5] * fD[oo][5];
        u64 b0 = packkey(dot0, nA);
        u64 b1 = packkey(dot1, nA + 1);
        u64 best = (b0 > b1) ? b0 : b1;
#pragma unroll
        for (int m = 1; m < 8; m <<= 1) {
            u64 o = shfl_xor_u64(best, m);
            if (o > best) best = o;
        }
        if (tx == 0) atomicMax(&d_key2[seg * 256 + o_base + oo], best);
    }
}

// ---------------------------------------------------------------------------
// gather + relu5 -> output  (one block per segment, 256 threads)
// ---------------------------------------------------------------------------
__global__ void k_relu5(float* __restrict__ out)
{
    __shared__ float G[256][3];
    int seg = blockIdx.x, c = threadIdx.x;
    u64 key = d_key2[seg * 256 + c];
    unsigned int idx = 0xFFFFFFFFu - (unsigned int)(key & 0xFFFFFFFFull);
    if (idx >= NPTS) idx = 0;
    float g0 = d_h5s[(size_t)c * NT3 + (size_t)idx * 3 + 0];
    float g1 = d_h5s[(size_t)c * NT3 + (size_t)idx * 3 + 1];
    float g2 = d_h5s[(size_t)c * NT3 + (size_t)idx * 3 + 2];
    G[c][0] = g0; G[c][1] = g1; G[c][2] = g2;
    __syncthreads();
    float a0 = 0.f, a1 = 0.f, a2 = 0.f;
    const float* w = d_wt + O_WR5;   // k-major: w[k*256 + c]
    for (int k = 0; k < 256; k++) {
        float ww = w[k * 256 + c];
        a0 += ww * G[k][0]; a1 += ww * G[k][1]; a2 += ww * G[k][2];
    }
    float dot = g0 * a0 + g1 * a1 + g2 * a2;
    float dn  = a0 * a0 + a1 * a1 + a2 * a2;
    float o0 = g0, o1 = g1, o2 = g2;
    if (dot < 0.f) {
        float s = dot / (dn + EPSV);
        o0 -= s * a0; o1 -= s * a1; o2 -= s * a2;
    }
    out[seg * 768 + c * 3 + 0] = o0;
    out[seg * 768 + c * 3 + 1] = o1;
    out[seg * 768 + c * 3 + 2] = o2;
}

// ---------------------------------------------------------------------------
// host launcher (same launch order as round 3 so ncu lands on a stage kernel)
// ---------------------------------------------------------------------------
extern "C" void kernel_launch(void* const* d_in, const int* in_sizes, int n_in,
                              void* d_out, int out_size)
{
    const float* x      = (const float*)d_in[0];
    const int*   radius = (const int*)d_in[1];

    cudaFuncSetAttribute(k_stage1, cudaFuncAttributeMaxDynamicSharedMemorySize, 114688);
    cudaFuncSetAttribute(k_stage2, cudaFuncAttributeMaxDynamicSharedMemorySize, 180224);

    k_initkeys<<<32, 256>>>();

    dim3 tb(32, 8);
    TList t128;
    t128.src[0] = (const float*)d_in[2];  t128.off[0] = O_W1F;
    t128.src[1] = (const float*)d_in[3];  t128.off[1] = O_W1D;
    t128.src[2] = (const float*)d_in[4];  t128.off[2] = O_W2F;
    t128.src[3] = (const float*)d_in[5];  t128.off[3] = O_W2D;
    t128.src[4] = (const float*)d_in[6];  t128.off[4] = O_W3;
    t128.src[5] = (const float*)d_in[7];  t128.off[5] = O_WD1;
    t128.src[6] = (const float*)d_in[8];  t128.off[6] = O_WR3;
    k_tmany<<<dim3(4, 4, 7), tb>>>(t128, 128, 128);

    TList t256;
    t256.src[0] = (const float*)d_in[9];   t256.off[0] = O_W4F;
    t256.src[1] = (const float*)d_in[10];  t256.off[1] = O_W4D;
    t256.src[2] = (const float*)d_in[11];  t256.off[2] = O_W5;
    t256.src[3] = (const float*)d_in[12];  t256.off[3] = O_WD2;
    t256.src[4] = (const float*)d_in[13];  t256.off[4] = O_WR5;
    t256.src[5] = t256.src[4];             t256.off[5] = O_WR5;  // unused (grid.z=5)
    t256.src[6] = t256.src[4];             t256.off[6] = O_WR5;
    k_tmany<<<dim3(8, 8, 5), tb>>>(t256, 256, 256);

    k_stage1<<<NPTS / 32, 256, 114688>>>(x, radius);
    k_relu3<<<NSEG, 128>>>();
    k_stage2<<<NPTS / 16, 256, 180224>>>(x, radius);
    k_relu5<<<NSEG, 256>>>((float*)d_out);
}